// round 1
// baseline (speedup 1.0000x reference)
#include <cuda_runtime.h>
#include <math.h>
#include <stdint.h>

// Problem constants
#define BB    64
#define SS    256
#define TT    256
#define HH    256
#define D1    160
#define LD    512
#define HIDD  512
#define FEATD 6144
#define MROWS (BB*SS)   // 16384
#define BT    (BB*TT)   // 16384

// ---------------- scratch (single __device__ global, offsets in floats) -----
#define O_IVEC  ((size_t)0)
#define SZ_IVEC ((size_t)MROWS*D1)                 // 2,621,440
#define O_XGF   (O_IVEC + SZ_IVEC)
#define SZ_XG   ((size_t)MROWS*1024)               // 16,777,216
#define O_XGB   (O_XGF + SZ_XG)
#define O_VEC1  (O_XGB + SZ_XG)
#define SZ_VEC  ((size_t)MROWS*LD)                 // 8,388,608
#define O_VEC2  (O_VEC1 + SZ_VEC)
#define O_HID   (O_VEC2 + SZ_VEC)
#define SZ_HID  ((size_t)BT*HIDD)                  // 8,388,608
#define O_RHID  (O_HID + SZ_HID)
#define O_WHHT  (O_RHID + SZ_HID)
#define SZ_WHHT ((size_t)HH*HH*4)                  // 262,144 per LSTM
#define O_HTF   (O_WHHT + 4*SZ_WHHT)
#define SZ_HT   ((size_t)2*HH*BB)                  // 32,768 (double-buffered)
#define O_HTB   (O_HTF + SZ_HT)
#define O_OWT   (O_HTB + SZ_HT)
#define SZ_OWT  ((size_t)HIDD*96)                  // 49,152
#define SCRATCH_TOTAL (O_OWT + SZ_OWT)

__device__ float g_scratch[SCRATCH_TOTAL];

// grid barrier state
__device__ unsigned g_cnt;
__device__ volatile unsigned g_flag;

// ---------------- embedding: ivec = [wlookup[word] | plookup[pos]] ----------
__global__ void k_embed(const int* __restrict__ wid, const int* __restrict__ pid,
                        const float* __restrict__ wl, const float* __restrict__ pl,
                        float* __restrict__ iv)
{
    int i = blockIdx.x * 256 + threadIdx.x;
    if (i >= MROWS * D1) return;
    int d  = i % D1;
    int bs = i / D1;
    iv[i] = (d < 128) ? wl[(size_t)wid[bs] * 128 + d]
                      : pl[(size_t)pid[bs] * 32 + (d - 128)];
}

// ---------------- Whh -> gate-interleaved transpose: wt[k][jh][gate] --------
__global__ void k_whht(const float* __restrict__ w, float* __restrict__ o)
{
    int i = blockIdx.x * 256 + threadIdx.x;
    if (i >= HH * HH * 4) return;
    int k   = i >> 10;
    int rem = i & 1023;
    int jh  = rem >> 2;
    int g   = rem & 3;
    o[i] = w[((g << 8) + jh) * HH + k];   // Whh[(g*256+jh)][k]
}

// ---------------- combined transposed output weights owT[h][o] --------------
__global__ void k_owt(const float* __restrict__ outL, const float* __restrict__ routL,
                      float* __restrict__ owT)
{
    int i = blockIdx.x * 256 + threadIdx.x;
    if (i >= HIDD * 96) return;
    int h = i / 96, o = i % 96;
    owT[i] = (o < 3) ? outL[o * HIDD + h] : routL[(o - 3) * HIDD + h];
}

// ---------------- reset barrier + zero h state -------------------------------
__global__ void k_reset(float* __restrict__ hTf, float* __restrict__ hTb)
{
    int i = blockIdx.x * 256 + threadIdx.x;
    if (i == 0) { g_cnt = 0; g_flag = 0; }
    if (i < 2 * (int)SZ_HT) {
        if (i < (int)SZ_HT) hTf[i] = 0.f;
        else                hTb[i - SZ_HT] = 0.f;
    }
}

// ---------------- persistent biLSTM recurrence (both directions) -------------
// grid = 128 blocks (co-resident), 256 threads.
// blocks 0..63: forward, 64..127: backward.
// block -> (b-slice of 16) x (jh-slice of 16); thread -> one (b, jh) cell.
// c state lives in a register for the whole sequence.
__global__ void __launch_bounds__(256, 1) k_recur(
    const float* __restrict__ xgf, const float* __restrict__ xgb,
    const float* __restrict__ wtf, const float* __restrict__ wtb,
    float* __restrict__ vec, float* __restrict__ hTf, float* __restrict__ hTb)
{
    extern __shared__ float sm[];
    float* sh_w = sm;            // [256 k][16 jh][4 gates] = 16384 floats
    float* sh_h = sm + 16384;    // [256 k][16 b]           =  4096 floats

    const int tid = threadIdx.x;
    const int dir = blockIdx.x >> 6;
    const int sub = blockIdx.x & 63;
    const int b0  = (sub & 3) * 16;
    const int jh0 = (sub >> 2) * 16;
    const int bl  = tid >> 4, jhl = tid & 15;
    const int b   = b0 + bl,  jh  = jh0 + jhl;

    const float* xg = dir ? xgb : xgf;
    const float* wt = dir ? wtb : wtf;
    float*       hT = dir ? hTb : hTf;

    // load this block's Whh slice once (constant across all 256 steps)
    for (int idx = tid; idx < 16384; idx += 256) {
        int k = idx >> 6, r = idx & 63;
        sh_w[idx] = wt[k * 1024 + jh0 * 4 + r];
    }

    float c = 0.f;
    unsigned epoch = 0;
    __syncthreads();

    for (int it = 0; it < SS; ++it) {
        const float* hcur = hT + (it & 1) * (HH * BB);
        float*       hnxt = hT + ((it & 1) ^ 1) * (HH * BB);

        // stage h^T slice (written by other SMs last step -> bypass L1)
        for (int idx = tid; idx < 4096; idx += 256) {
            int k = idx >> 4, bb = idx & 15;
            sh_h[idx] = __ldcg(hcur + k * 64 + b0 + bb);
        }
        __syncthreads();

        const int s = dir ? (SS - 1 - it) : it;
        const float* xr = xg + ((size_t)(b * SS + s)) * 1024 + jh;
        float ai = __ldg(xr +   0);
        float af = __ldg(xr + 256);
        float ag = __ldg(xr + 512);
        float ao = __ldg(xr + 768);

        const float* whp = sh_w + jhl * 4;
        const float* shp = sh_h + bl;
        #pragma unroll 8
        for (int k = 0; k < HH; ++k) {
            float  hv = shp[k * 16];
            float4 w  = *reinterpret_cast<const float4*>(whp + k * 64);
            ai = fmaf(hv, w.x, ai);
            af = fmaf(hv, w.y, af);
            ag = fmaf(hv, w.z, ag);
            ao = fmaf(hv, w.w, ao);
        }

        float ig = 1.f / (1.f + expf(-ai));
        float fg = 1.f / (1.f + expf(-af));
        float gv = tanhf(ag);
        float og = 1.f / (1.f + expf(-ao));
        c = fmaf(fg, c, ig * gv);
        float h = og * tanhf(c);

        vec[((size_t)(b * SS + s)) * LD + (dir << 8) + jh] = h;
        __stcg(hnxt + jh * 64 + b, h);

        // ---- software grid barrier (monotone flag) ----
        __threadfence();
        __syncthreads();
        epoch += gridDim.x;
        if (tid == 0) {
            unsigned arrived = atomicAdd(&g_cnt, 1) + 1;
            if (arrived == epoch) {
                __threadfence();
                g_flag = epoch;
            } else {
                while (g_flag < epoch) { }
                __threadfence();
            }
        }
        __syncthreads();
    }
}

// ---------------- SGEMM: C[m][n] = sum_k A[m][k]*W[n][k] (+bias) (tanh) ------
// 128x128x8 tiles, 256 threads, 8x8 per thread, register prefetch.
// GATHER=true: A row m=(b,t) is the 12x512 feat gather from vsrc via fidx.
template<int EPI, bool GATHER>
__global__ void __launch_bounds__(256) k_sgemm(
    const float* __restrict__ A, const float* __restrict__ W,
    const float* __restrict__ b1, const float* __restrict__ b2,
    float* __restrict__ C, int M, int N, int K,
    const int* __restrict__ fidx, const float* __restrict__ vsrc)
{
    __shared__ __align__(16) float As[8 * 128];
    __shared__ __align__(16) float Bs[8 * 128];

    const int tid  = threadIdx.x;
    const int row0 = blockIdx.y * 128;
    const int col0 = blockIdx.x * 128;
    const int lr   = tid >> 1;
    const int lk   = (tid & 1) * 4;
    const int ty   = tid >> 4;
    const int tx   = tid & 15;

    float acc[8][8];
    #pragma unroll
    for (int i = 0; i < 8; ++i)
        #pragma unroll
        for (int j = 0; j < 8; ++j) acc[i][j] = 0.f;

    auto loadA = [&](int k0) -> float4 {
        if (!GATHER) {
            return *reinterpret_cast<const float4*>(A + (size_t)(row0 + lr) * K + k0 + lk);
        } else {
            int m    = row0 + lr;
            int kk   = k0 + lk;
            int slot = kk >> 9;
            int idx  = __ldg(fidx + m * 12 + slot);
            int bb   = m >> 8;
            return *reinterpret_cast<const float4*>(
                vsrc + ((size_t)((bb << 8) + idx)) * 512 + (kk & 511));
        }
    };
    auto loadB = [&](int k0) -> float4 {
        return *reinterpret_cast<const float4*>(W + (size_t)(col0 + lr) * K + k0 + lk);
    };

    float4 ra = loadA(0);
    float4 rb = loadB(0);

    for (int k0 = 0; k0 < K; k0 += 8) {
        As[(lk + 0) * 128 + lr] = ra.x;
        As[(lk + 1) * 128 + lr] = ra.y;
        As[(lk + 2) * 128 + lr] = ra.z;
        As[(lk + 3) * 128 + lr] = ra.w;
        Bs[(lk + 0) * 128 + lr] = rb.x;
        Bs[(lk + 1) * 128 + lr] = rb.y;
        Bs[(lk + 2) * 128 + lr] = rb.z;
        Bs[(lk + 3) * 128 + lr] = rb.w;
        __syncthreads();

        if (k0 + 8 < K) { ra = loadA(k0 + 8); rb = loadB(k0 + 8); }

        #pragma unroll
        for (int k = 0; k < 8; ++k) {
            float4 a0 = *reinterpret_cast<const float4*>(As + k * 128 + ty * 4);
            float4 a1 = *reinterpret_cast<const float4*>(As + k * 128 + 64 + ty * 4);
            float4 c0 = *reinterpret_cast<const float4*>(Bs + k * 128 + tx * 4);
            float4 c1 = *reinterpret_cast<const float4*>(Bs + k * 128 + 64 + tx * 4);
            float av[8] = {a0.x, a0.y, a0.z, a0.w, a1.x, a1.y, a1.z, a1.w};
            float bv[8] = {c0.x, c0.y, c0.z, c0.w, c1.x, c1.y, c1.z, c1.w};
            #pragma unroll
            for (int i = 0; i < 8; ++i)
                #pragma unroll
                for (int j = 0; j < 8; ++j)
                    acc[i][j] = fmaf(av[i], bv[j], acc[i][j]);
        }
        __syncthreads();
    }

    float bias[8];
    #pragma unroll
    for (int j = 0; j < 8; ++j) {
        int cc = col0 + ((j < 4) ? tx * 4 + j : 64 + tx * 4 + (j - 4));
        float bbv = b1 ? b1[cc] : 0.f;
        if (b2) bbv += b2[cc];
        bias[j] = bbv;
    }
    #pragma unroll
    for (int i = 0; i < 8; ++i) {
        int r = row0 + ((i < 4) ? ty * 4 + i : 64 + ty * 4 + (i - 4));
        #pragma unroll
        for (int j = 0; j < 8; ++j) {
            int cc = col0 + ((j < 4) ? tx * 4 + j : 64 + tx * 4 + (j - 4));
            float v = acc[i][j] + bias[j];
            if (EPI == 1) v = tanhf(v);
            C[(size_t)r * N + cc] = v;
        }
    }
}

// ---------------- output head: out[3] | rout[93] per (b,t) -------------------
__global__ void k_out(const float* __restrict__ hid, const float* __restrict__ rhid,
                      const float* __restrict__ owT, const float* __restrict__ ob,
                      const float* __restrict__ rb, float* __restrict__ out)
{
    int bt = blockIdx.x;
    __shared__ float sh[1024];
    for (int i = threadIdx.x; i < 512; i += 128) sh[i]       = hid[(size_t)bt * 512 + i];
    for (int i = threadIdx.x; i < 512; i += 128) sh[512 + i] = rhid[(size_t)bt * 512 + i];
    __syncthreads();
    int o = threadIdx.x;
    if (o < 96) {
        const float* base = (o < 3) ? sh : sh + 512;
        float acc = 0.f;
        #pragma unroll 8
        for (int h = 0; h < 512; ++h)
            acc = fmaf(owT[h * 96 + o], base[h], acc);
        if (o < 3) out[(size_t)bt * 3 + o] = acc + ob[o];
        else       out[(size_t)BT * 3 + (size_t)bt * 93 + (o - 3)] = acc + rb[o - 3];
    }
}

// ---------------- launch ------------------------------------------------------
extern "C" void kernel_launch(void* const* d_in, const int* in_sizes, int n_in,
                              void* d_out, int out_size)
{
    const int*   wid   = (const int*)d_in[0];
    const int*   pid   = (const int*)d_in[1];
    const int*   fidx  = (const int*)d_in[2];
    const float* wl    = (const float*)d_in[3];
    const float* pl    = (const float*)d_in[4];
    const float* Wih1f = (const float*)d_in[5];
    const float* Whh1f = (const float*)d_in[6];
    const float* bih1f = (const float*)d_in[7];
    const float* bhh1f = (const float*)d_in[8];
    const float* Wih1b = (const float*)d_in[9];
    const float* Whh1b = (const float*)d_in[10];
    const float* bih1b = (const float*)d_in[11];
    const float* bhh1b = (const float*)d_in[12];
    const float* Wih2f = (const float*)d_in[13];
    const float* Whh2f = (const float*)d_in[14];
    const float* bih2f = (const float*)d_in[15];
    const float* bhh2f = (const float*)d_in[16];
    const float* Wih2b = (const float*)d_in[17];
    const float* Whh2b = (const float*)d_in[18];
    const float* bih2b = (const float*)d_in[19];
    const float* bhh2b = (const float*)d_in[20];
    const float* hidL  = (const float*)d_in[21];
    const float* hidB  = (const float*)d_in[22];
    const float* outL  = (const float*)d_in[23];
    const float* outB  = (const float*)d_in[24];
    const float* rhidL = (const float*)d_in[25];
    const float* rhidB = (const float*)d_in[26];
    const float* routL = (const float*)d_in[27];
    const float* routB = (const float*)d_in[28];
    float* out = (float*)d_out;

    float* scr = nullptr;
    cudaGetSymbolAddress((void**)&scr, g_scratch);
    float* ivec  = scr + O_IVEC;
    float* xgf   = scr + O_XGF;
    float* xgb   = scr + O_XGB;
    float* vec1  = scr + O_VEC1;
    float* vec2  = scr + O_VEC2;
    float* hid   = scr + O_HID;
    float* rhid  = scr + O_RHID;
    float* whht  = scr + O_WHHT;
    float* hTf   = scr + O_HTF;
    float* hTb   = scr + O_HTB;
    float* owT   = scr + O_OWT;

    cudaFuncSetAttribute(k_recur, cudaFuncAttributeMaxDynamicSharedMemorySize, 81920);

    // embeddings + weight prep
    k_embed<<<(MROWS * D1 + 255) / 256, 256>>>(wid, pid, wl, pl, ivec);
    k_whht<<<1024, 256>>>(Whh1f, whht + 0 * SZ_WHHT);
    k_whht<<<1024, 256>>>(Whh1b, whht + 1 * SZ_WHHT);
    k_whht<<<1024, 256>>>(Whh2f, whht + 2 * SZ_WHHT);
    k_whht<<<1024, 256>>>(Whh2b, whht + 3 * SZ_WHHT);
    k_owt<<<(HIDD * 96 + 255) / 256, 256>>>(outL, routL, owT);

    // layer 1
    dim3 g1(1024 / 128, MROWS / 128);
    k_sgemm<0, false><<<g1, 256>>>(ivec, Wih1f, bih1f, bhh1f, xgf, MROWS, 1024, D1, nullptr, nullptr);
    k_sgemm<0, false><<<g1, 256>>>(ivec, Wih1b, bih1b, bhh1b, xgb, MROWS, 1024, D1, nullptr, nullptr);
    k_reset<<<256, 256>>>(hTf, hTb);
    k_recur<<<128, 256, 81920>>>(xgf, xgb, whht + 0 * SZ_WHHT, whht + 1 * SZ_WHHT, vec1, hTf, hTb);

    // layer 2
    k_sgemm<0, false><<<g1, 256>>>(vec1, Wih2f, bih2f, bhh2f, xgf, MROWS, 1024, LD, nullptr, nullptr);
    k_sgemm<0, false><<<g1, 256>>>(vec1, Wih2b, bih2b, bhh2b, xgb, MROWS, 1024, LD, nullptr, nullptr);
    k_reset<<<256, 256>>>(hTf, hTb);
    k_recur<<<128, 256, 81920>>>(xgf, xgb, whht + 2 * SZ_WHHT, whht + 3 * SZ_WHHT, vec2, hTf, hTb);

    // MLP head with fused gather + tanh epilogue
    dim3 g2(HIDD / 128, BT / 128);
    k_sgemm<1, true><<<g2, 256>>>(nullptr, hidL,  hidB,  nullptr, hid,  BT, HIDD, FEATD, fidx, vec2);
    k_sgemm<1, true><<<g2, 256>>>(nullptr, rhidL, rhidB, nullptr, rhid, BT, HIDD, FEATD, fidx, vec2);

    // output head
    k_out<<<BT, 128>>>(hid, rhid, owT, outB, routB, out);
}

// round 3
// speedup vs baseline: 1.4601x; 1.4601x over previous
#include <cuda_runtime.h>
#include <cuda_bf16.h>
#include <math.h>
#include <stdint.h>

// ---------------- problem constants ----------------
#define BBATCH 64
#define SSEQ   256
#define HHID   256
#define MROWS  16384
#define BTROWS 16384

// ---------------- fp32 scratch ----------------
#define O_XGF   ((size_t)0)
#define SZ_XG   ((size_t)MROWS*1024)
#define O_XGB   (O_XGF+SZ_XG)
#define O_VEC1  (O_XGB+SZ_XG)
#define SZ_VEC  ((size_t)MROWS*512)
#define O_VEC2  (O_VEC1+SZ_VEC)
#define O_HID   (O_VEC2+SZ_VEC)
#define SZ_HID  ((size_t)BTROWS*512)
#define O_RHID  (O_HID+SZ_HID)
#define O_WHHT  (O_RHID+SZ_HID)
#define SZ_WHHT ((size_t)HHID*HHID*4)
#define O_HTF   (O_WHHT+4*SZ_WHHT)
#define SZ_HT   ((size_t)2*HHID*BBATCH)
#define O_HTB   (O_HTF+SZ_HT)
#define O_OWT   (O_HTB+SZ_HT)
#define SZ_OWT  ((size_t)512*96)
#define O_BS1   (O_OWT+SZ_OWT)
#define O_BS2   (O_BS1+2048)
#define O_BSM   (O_BS2+2048)
#define F32_TOTAL (O_BSM+1024)

__device__ float g_f32[F32_TOTAL];

// ---------------- bf16 scratch ----------------
#define B_IVHI ((size_t)0)
#define SZ_IV  ((size_t)MROWS*192)
#define B_IVLO (B_IVHI+SZ_IV)
#define B_AVHI (B_IVLO+SZ_IV)
#define SZ_AV  ((size_t)MROWS*512)
#define B_AVLO (B_AVHI+SZ_AV)
#define B_W1HI (B_AVLO+SZ_AV)
#define SZ_W1  ((size_t)2048*192)
#define B_W1LO (B_W1HI+SZ_W1)
#define B_W2HI (B_W1LO+SZ_W1)
#define SZ_W2  ((size_t)2048*512)
#define B_W2LO (B_W2HI+SZ_W2)
#define B_WMHI (B_W2LO+SZ_W2)
#define SZ_WM  ((size_t)1024*6144)
#define B_WMLO (B_WMHI+SZ_WM)
#define BF_TOTAL (B_WMLO+SZ_WM)

__device__ __nv_bfloat16 g_bf[BF_TOTAL];

// grid barrier state (recurrence)
__device__ unsigned g_cnt;
__device__ volatile unsigned g_flag;

// ---------------- small prep kernels ----------------
__global__ void k_embed_split(const int* __restrict__ wid, const int* __restrict__ pid,
                              const float* __restrict__ wl, const float* __restrict__ pl,
                              __nv_bfloat16* __restrict__ hi, __nv_bfloat16* __restrict__ lo)
{
    int i = blockIdx.x * 256 + threadIdx.x;
    if (i >= MROWS * 192) return;
    int col = i % 192, bs = i / 192;
    float v = 0.f;
    if (col < 128)      v = wl[(size_t)wid[bs] * 128 + col];
    else if (col < 160) v = pl[(size_t)pid[bs] * 32 + (col - 128)];
    __nv_bfloat16 h = __float2bfloat16(v);
    hi[i] = h;
    lo[i] = __float2bfloat16(v - __bfloat162float(h));
}

__global__ void k_split(const float* __restrict__ x,
                        __nv_bfloat16* __restrict__ hi, __nv_bfloat16* __restrict__ lo, int n)
{
    int i = blockIdx.x * 256 + threadIdx.x;
    if (i >= n) return;
    float v = x[i];
    __nv_bfloat16 h = __float2bfloat16(v);
    hi[i] = h;
    lo[i] = __float2bfloat16(v - __bfloat162float(h));
}

__global__ void k_wsplit(const float* __restrict__ W0, const float* __restrict__ W1,
                         int N0, int Ksrc, int Kpad,
                         __nv_bfloat16* __restrict__ hi, __nv_bfloat16* __restrict__ lo, int total)
{
    int i = blockIdx.x * 256 + threadIdx.x;
    if (i >= total) return;
    int row = i / Kpad, col = i % Kpad;
    float v = 0.f;
    if (col < Ksrc)
        v = (row < N0) ? W0[(size_t)row * Ksrc + col]
                       : W1[(size_t)(row - N0) * Ksrc + col];
    __nv_bfloat16 h = __float2bfloat16(v);
    hi[i] = h;
    lo[i] = __float2bfloat16(v - __bfloat162float(h));
}

__global__ void k_bias2(const float* a, const float* b, const float* c, const float* d,
                        float* __restrict__ o)
{
    int i = blockIdx.x * 256 + threadIdx.x;
    if (i >= 2048) return;
    o[i] = (i < 1024) ? a[i] + b[i] : c[i - 1024] + d[i - 1024];
}

__global__ void k_bcat(const float* a, const float* b, float* __restrict__ o)
{
    int i = blockIdx.x * 256 + threadIdx.x;
    if (i >= 1024) return;
    o[i] = (i < 512) ? a[i] : b[i - 512];
}

__global__ void k_whht(const float* __restrict__ w, float* __restrict__ o)
{
    int i = blockIdx.x * 256 + threadIdx.x;
    if (i >= HHID * HHID * 4) return;
    int k = i >> 10, rem = i & 1023, jh = rem >> 2, g = rem & 3;
    o[i] = w[((g << 8) + jh) * HHID + k];
}

__global__ void k_owt(const float* __restrict__ outL, const float* __restrict__ routL,
                      float* __restrict__ owT)
{
    int i = blockIdx.x * 256 + threadIdx.x;
    if (i >= 512 * 96) return;
    int h = i / 96, o = i % 96;
    owT[i] = (o < 3) ? outL[o * 512 + h] : routL[(o - 3) * 512 + h];
}

__global__ void k_reset(float* __restrict__ hTf, float* __restrict__ hTb)
{
    int i = blockIdx.x * 256 + threadIdx.x;
    if (i == 0) { g_cnt = 0; g_flag = 0; }
    if (i < 2 * (int)SZ_HT) {
        if (i < (int)SZ_HT) hTf[i] = 0.f;
        else                hTb[i - SZ_HT] = 0.f;
    }
}

// ---------------- persistent biLSTM recurrence -------------------------------
__global__ void __launch_bounds__(256, 1) k_recur(
    const float* __restrict__ xgf, const float* __restrict__ xgb,
    const float* __restrict__ wtf, const float* __restrict__ wtb,
    float* __restrict__ vec, float* __restrict__ hTf, float* __restrict__ hTb)
{
    extern __shared__ char s_raw[];
    float* sm = (float*)s_raw;
    float* sh_w = sm;            // [256 k][16 jh][4 gates]
    float* sh_h = sm + 16384;    // [256 k][16 b]

    const int tid = threadIdx.x;
    const int dir = blockIdx.x >> 6;
    const int sub = blockIdx.x & 63;
    const int b0  = (sub & 3) * 16;
    const int jh0 = (sub >> 2) * 16;
    const int bl  = tid >> 4, jhl = tid & 15;
    const int b   = b0 + bl,  jh  = jh0 + jhl;

    const float* xg = dir ? xgb : xgf;
    const float* wt = dir ? wtb : wtf;
    float*       hT = dir ? hTb : hTf;

    for (int idx = tid; idx < 16384; idx += 256) {
        int k = idx >> 6, r = idx & 63;
        sh_w[idx] = wt[k * 1024 + jh0 * 4 + r];
    }

    float c = 0.f;
    unsigned epoch = 0;
    __syncthreads();

    for (int it = 0; it < SSEQ; ++it) {
        const float* hcur = hT + (it & 1) * (HHID * BBATCH);
        float*       hnxt = hT + ((it & 1) ^ 1) * (HHID * BBATCH);

        for (int idx = tid; idx < 4096; idx += 256) {
            int k = idx >> 4, bb = idx & 15;
            sh_h[idx] = __ldcg(hcur + k * 64 + b0 + bb);
        }
        __syncthreads();

        const int s = dir ? (SSEQ - 1 - it) : it;
        const float* xr = xg + ((size_t)(b * SSEQ + s)) * 1024 + jh;
        float ai = __ldg(xr +   0);
        float af = __ldg(xr + 256);
        float ag = __ldg(xr + 512);
        float ao = __ldg(xr + 768);

        const float* whp = sh_w + jhl * 4;
        const float* shp = sh_h + bl;
        #pragma unroll 8
        for (int k = 0; k < HHID; ++k) {
            float  hv = shp[k * 16];
            float4 w  = *reinterpret_cast<const float4*>(whp + k * 64);
            ai = fmaf(hv, w.x, ai);
            af = fmaf(hv, w.y, af);
            ag = fmaf(hv, w.z, ag);
            ao = fmaf(hv, w.w, ao);
        }

        float ig = 1.f / (1.f + expf(-ai));
        float fg = 1.f / (1.f + expf(-af));
        float gv = tanhf(ag);
        float og = 1.f / (1.f + expf(-ao));
        c = fmaf(fg, c, ig * gv);
        float h = og * tanhf(c);

        vec[((size_t)(b * SSEQ + s)) * 512 + (dir << 8) + jh] = h;
        __stcg(hnxt + jh * 64 + b, h);

        __threadfence();
        __syncthreads();
        epoch += gridDim.x;
        if (tid == 0) {
            unsigned arrived = atomicAdd(&g_cnt, 1) + 1;
            if (arrived == epoch) {
                __threadfence();
                g_flag = epoch;
            } else {
                while (g_flag < epoch) { }
                __threadfence();
            }
        }
        __syncthreads();
    }
}

// ---------------- HMMA bf16 3-product split GEMM ----------------------------
// C[m][n] = sum_k A[m][k]*W[n][k] + bias[n]; A ~ Ahi+Alo, W ~ Whi+Wlo.
// Products: Ahi*Whi + Ahi*Wlo + Alo*Whi accumulated in fp32 registers.
// Block tile 128x128, 8 warps (warp tile 32x64), K-chunk 64.
// SMEM rows padded to 72 bf16 (36 words) -> conflict-free fragment loads.
// GATHER: A row m gathers 12 x 512-wide slots from vec via fidx.
// Output col < halfN -> C0 else C1 (both row-major, ld = halfN).
#define TROW 72          // padded row, elements
#define TROWB 144        // padded row, bytes
#define TILEB 18432      // 128*144 bytes per tile

__device__ __forceinline__ void mma16816(float* d, const uint32_t* a, const uint32_t* b) {
    asm volatile(
        "mma.sync.aligned.m16n8k16.row.col.f32.bf16.bf16.f32 "
        "{%0,%1,%2,%3}, {%4,%5,%6,%7}, {%8,%9}, {%0,%1,%2,%3};"
        : "+f"(d[0]), "+f"(d[1]), "+f"(d[2]), "+f"(d[3])
        : "r"(a[0]), "r"(a[1]), "r"(a[2]), "r"(a[3]), "r"(b[0]), "r"(b[1]));
}

template<bool GATHER, bool TANH>
__global__ void __launch_bounds__(256, 2) k_hmma(
    const __nv_bfloat16* __restrict__ Ahi, const __nv_bfloat16* __restrict__ Alo,
    const __nv_bfloat16* __restrict__ Whi, const __nv_bfloat16* __restrict__ Wlo,
    const float* __restrict__ bias, float* __restrict__ C0, float* __restrict__ C1,
    int halfN, int Kpad, const int* __restrict__ fidx)
{
    extern __shared__ __align__(16) char smem[];
    // tiles: [0]=Ahi [1]=Alo [2]=Bhi [3]=Blo, each 128 rows x 144B
    const int tid  = threadIdx.x;
    const int wid  = tid >> 5;
    const int lane = tid & 31;
    const int grp  = lane >> 2;      // 0..7
    const int quad = lane & 3;       // 0..3
    const int row0 = blockIdx.y * 128;
    const int n0   = blockIdx.x * 128;
    const int wm   = (wid & 3) * 32;
    const int wn   = (wid >> 2) * 64;

    const int KU = Kpad >> 3;        // uint4 per source row
    const uint4* A4h = (const uint4*)Ahi;
    const uint4* A4l = (const uint4*)Alo;
    const uint4* W4h = (const uint4*)Whi;
    const uint4* W4l = (const uint4*)Wlo;

    float acc[2][8][4];
    #pragma unroll
    for (int i = 0; i < 2; ++i)
        #pragma unroll
        for (int j = 0; j < 8; ++j)
            #pragma unroll
            for (int q = 0; q < 4; ++q) acc[i][j][q] = 0.f;

    const int nch = Kpad >> 6;
    for (int c = 0; c < nch; ++c) {
        const int k0  = c << 6;
        const int ku0 = k0 >> 3;

        // ---- global -> smem (4 tiles, 1024 uint4 each) ----
        #pragma unroll
        for (int u = tid; u < 2048; u += 256) {      // A hi/lo
            int sel = u >> 10;
            int v = u & 1023;
            int r = v >> 3, j = v & 7;
            uint4 val;
            if (GATHER) {
                int m    = row0 + r;
                int slot = k0 >> 9;
                int idx  = __ldg(fidx + m * 12 + slot);
                int srow = ((m >> 8) << 8) + idx;
                const uint4* src = sel ? A4l : A4h;
                val = src[(size_t)srow * 64 + ((k0 & 511) >> 3) + j];
            } else {
                const uint4* src = sel ? A4l : A4h;
                val = src[(size_t)(row0 + r) * KU + ku0 + j];
            }
            *(uint4*)(smem + sel * TILEB + r * TROWB + j * 16) = val;
        }
        #pragma unroll
        for (int u = tid; u < 2048; u += 256) {      // B hi/lo
            int sel = u >> 10;
            int v = u & 1023;
            int r = v >> 3, j = v & 7;
            const uint4* src = sel ? W4l : W4h;
            uint4 val = src[(size_t)(n0 + r) * KU + ku0 + j];
            *(uint4*)(smem + (2 + sel) * TILEB + r * TROWB + j * 16) = val;
        }
        __syncthreads();

        // ---- 3 products x 4 k-steps of m16n8k16 ----
        #pragma unroll
        for (int p = 0; p < 3; ++p) {
            const uint32_t* A32 = (const uint32_t*)(smem + (p == 2 ? TILEB : 0));
            const uint32_t* B32 = (const uint32_t*)(smem + (p == 1 ? 3 : 2) * TILEB);
            #pragma unroll
            for (int ks = 0; ks < 4; ++ks) {
                const int kw = ks * 8 + quad;   // word offset within row
                uint32_t a[2][4];
                #pragma unroll
                for (int mt = 0; mt < 2; ++mt) {
                    int r = wm + mt * 16 + grp;
                    a[mt][0] = A32[r * 36 + kw];
                    a[mt][1] = A32[(r + 8) * 36 + kw];
                    a[mt][2] = A32[r * 36 + kw + 4];
                    a[mt][3] = A32[(r + 8) * 36 + kw + 4];
                }
                uint32_t b[8][2];
                #pragma unroll
                for (int nt = 0; nt < 8; ++nt) {
                    int n = wn + nt * 8 + grp;
                    b[nt][0] = B32[n * 36 + kw];
                    b[nt][1] = B32[n * 36 + kw + 4];
                }
                #pragma unroll
                for (int mt = 0; mt < 2; ++mt)
                    #pragma unroll
                    for (int nt = 0; nt < 8; ++nt)
                        mma16816(acc[mt][nt], a[mt], b[nt]);
            }
        }
        __syncthreads();
    }

    // ---- epilogue: bias (+tanh), route to C0/C1 ----
    const int gbase = n0 + wn;                // warp's 64-col span start
    float* Co;
    int cbase;
    if (gbase < halfN) { Co = C0; cbase = gbase; }
    else               { Co = C1; cbase = gbase - halfN; }

    #pragma unroll
    for (int mt = 0; mt < 2; ++mt) {
        int r = row0 + wm + mt * 16 + grp;
        #pragma unroll
        for (int nt = 0; nt < 8; ++nt) {
            int gc = gbase + nt * 8 + quad * 2;
            float b0v = bias[gc], b1v = bias[gc + 1];
            float v0 = acc[mt][nt][0] + b0v;
            float v1 = acc[mt][nt][1] + b1v;
            float v2 = acc[mt][nt][2] + b0v;
            float v3 = acc[mt][nt][3] + b1v;
            if (TANH) { v0 = tanhf(v0); v1 = tanhf(v1); v2 = tanhf(v2); v3 = tanhf(v3); }
            int cc = cbase + nt * 8 + quad * 2;
            *(float2*)(Co + (size_t)r * halfN + cc)       = make_float2(v0, v1);
            *(float2*)(Co + (size_t)(r + 8) * halfN + cc) = make_float2(v2, v3);
        }
    }
}

// ---------------- output head ------------------------------------------------
__global__ void k_out(const float* __restrict__ hid, const float* __restrict__ rhid,
                      const float* __restrict__ owT, const float* __restrict__ ob,
                      const float* __restrict__ rb, float* __restrict__ out)
{
    int bt = blockIdx.x;
    __shared__ float sh[1024];
    for (int i = threadIdx.x; i < 512; i += 128) sh[i]       = hid[(size_t)bt * 512 + i];
    for (int i = threadIdx.x; i < 512; i += 128) sh[512 + i] = rhid[(size_t)bt * 512 + i];
    __syncthreads();
    int o = threadIdx.x;
    if (o < 96) {
        const float* base = (o < 3) ? sh : sh + 512;
        float acc = 0.f;
        #pragma unroll 8
        for (int h = 0; h < 512; ++h)
            acc = fmaf(owT[h * 96 + o], base[h], acc);
        if (o < 3) out[(size_t)bt * 3 + o] = acc + ob[o];
        else       out[(size_t)BTROWS * 3 + (size_t)bt * 93 + (o - 3)] = acc + rb[o - 3];
    }
}

// ---------------- launch ------------------------------------------------------
extern "C" void kernel_launch(void* const* d_in, const int* in_sizes, int n_in,
                              void* d_out, int out_size)
{
    const int*   wid   = (const int*)d_in[0];
    const int*   pid   = (const int*)d_in[1];
    const int*   fidx  = (const int*)d_in[2];
    const float* wl    = (const float*)d_in[3];
    const float* pl    = (const float*)d_in[4];
    const float* Wih1f = (const float*)d_in[5];
    const float* Whh1f = (const float*)d_in[6];
    const float* bih1f = (const float*)d_in[7];
    const float* bhh1f = (const float*)d_in[8];
    const float* Wih1b = (const float*)d_in[9];
    const float* Whh1b = (const float*)d_in[10];
    const float* bih1b = (const float*)d_in[11];
    const float* bhh1b = (const float*)d_in[12];
    const float* Wih2f = (const float*)d_in[13];
    const float* Whh2f = (const float*)d_in[14];
    const float* bih2f = (const float*)d_in[15];
    const float* bhh2f = (const float*)d_in[16];
    const float* Wih2b = (const float*)d_in[17];
    const float* Whh2b = (const float*)d_in[18];
    const float* bih2b = (const float*)d_in[19];
    const float* bhh2b = (const float*)d_in[20];
    const float* hidL  = (const float*)d_in[21];
    const float* hidB  = (const float*)d_in[22];
    const float* outL  = (const float*)d_in[23];
    const float* outB  = (const float*)d_in[24];
    const float* rhidL = (const float*)d_in[25];
    const float* rhidB = (const float*)d_in[26];
    const float* routL = (const float*)d_in[27];
    const float* routB = (const float*)d_in[28];
    float* out = (float*)d_out;

    float* scr = nullptr;
    cudaGetSymbolAddress((void**)&scr, g_f32);
    __nv_bfloat16* bfp = nullptr;
    cudaGetSymbolAddress((void**)&bfp, g_bf);

    float* xgf  = scr + O_XGF;
    float* xgb  = scr + O_XGB;
    float* vec1 = scr + O_VEC1;
    float* vec2 = scr + O_VEC2;
    float* hid  = scr + O_HID;
    float* rhid = scr + O_RHID;
    float* whht = scr + O_WHHT;
    float* hTf  = scr + O_HTF;
    float* hTb  = scr + O_HTB;
    float* owT  = scr + O_OWT;
    float* bs1  = scr + O_BS1;
    float* bs2  = scr + O_BS2;
    float* bsm  = scr + O_BSM;

    __nv_bfloat16* ivhi = bfp + B_IVHI;
    __nv_bfloat16* ivlo = bfp + B_IVLO;
    __nv_bfloat16* avhi = bfp + B_AVHI;
    __nv_bfloat16* avlo = bfp + B_AVLO;
    __nv_bfloat16* w1hi = bfp + B_W1HI;
    __nv_bfloat16* w1lo = bfp + B_W1LO;
    __nv_bfloat16* w2hi = bfp + B_W2HI;
    __nv_bfloat16* w2lo = bfp + B_W2LO;
    __nv_bfloat16* wmhi = bfp + B_WMHI;
    __nv_bfloat16* wmlo = bfp + B_WMLO;

    cudaFuncSetAttribute(k_recur, cudaFuncAttributeMaxDynamicSharedMemorySize, 81920);
    cudaFuncSetAttribute(k_hmma<false, false>, cudaFuncAttributeMaxDynamicSharedMemorySize, 4 * TILEB);
    cudaFuncSetAttribute(k_hmma<true, true>,  cudaFuncAttributeMaxDynamicSharedMemorySize, 4 * TILEB);

    // --- prep: embeddings, weight splits, bias concats, recurrence weights ---
    k_embed_split<<<(MROWS * 192 + 255) / 256, 256>>>(wid, pid, wl, pl, ivhi, ivlo);
    k_whht<<<1024, 256>>>(Whh1f, whht + 0 * SZ_WHHT);
    k_whht<<<1024, 256>>>(Whh1b, whht + 1 * SZ_WHHT);
    k_whht<<<1024, 256>>>(Whh2f, whht + 2 * SZ_WHHT);
    k_whht<<<1024, 256>>>(Whh2b, whht + 3 * SZ_WHHT);
    k_owt<<<(512 * 96 + 255) / 256, 256>>>(outL, routL, owT);
    k_wsplit<<<(2048 * 192 + 255) / 256, 256>>>(Wih1f, Wih1b, 1024, 160, 192, w1hi, w1lo, 2048 * 192);
    k_wsplit<<<(2048 * 512 + 255) / 256, 256>>>(Wih2f, Wih2b, 1024, 512, 512, w2hi, w2lo, 2048 * 512);
    k_wsplit<<<(1024 * 6144 + 255) / 256, 256>>>(hidL, rhidL, 512, 6144, 6144, wmhi, wmlo, 1024 * 6144);
    k_bias2<<<8, 256>>>(bih1f, bhh1f, bih1b, bhh1b, bs1);
    k_bias2<<<8, 256>>>(bih2f, bhh2f, bih2b, bhh2b, bs2);
    k_bcat<<<4, 256>>>(hidB, rhidB, bsm);

    // --- layer 1: xg (both directions fused, N=2048), recurrence ---
    dim3 gx(16, 128);
    k_hmma<false, false><<<gx, 256, 4 * TILEB>>>(ivhi, ivlo, w1hi, w1lo, bs1, xgf, xgb, 1024, 192, nullptr);
    k_reset<<<256, 256>>>(hTf, hTb);
    k_recur<<<128, 256, 81920>>>(xgf, xgb, whht + 0 * SZ_WHHT, whht + 1 * SZ_WHHT, vec1, hTf, hTb);

    // --- layer 2 ---
    k_split<<<(MROWS * 512 + 255) / 256, 256>>>(vec1, avhi, avlo, MROWS * 512);
    k_hmma<false, false><<<gx, 256, 4 * TILEB>>>(avhi, avlo, w2hi, w2lo, bs2, xgf, xgb, 1024, 512, nullptr);
    k_reset<<<256, 256>>>(hTf, hTb);
    k_recur<<<128, 256, 81920>>>(xgf, xgb, whht + 2 * SZ_WHHT, whht + 3 * SZ_WHHT, vec2, hTf, hTb);

    // --- MLP head: gathered GEMM (hid|rhid fused, N=1024), tanh epilogue ---
    k_split<<<(MROWS * 512 + 255) / 256, 256>>>(vec2, avhi, avlo, MROWS * 512);
    dim3 gm(8, 128);
    k_hmma<true, true><<<gm, 256, 4 * TILEB>>>(avhi, avlo, wmhi, wmlo, bsm, hid, rhid, 512, 6144, fidx);

    // --- output head ---
    k_out<<<BTROWS, 128>>>(hid, rhid, owT, outB, routB, out);
}

// round 4
// speedup vs baseline: 1.4809x; 1.0143x over previous
#include <cuda_runtime.h>
#include <cuda_bf16.h>
#include <math.h>
#include <stdint.h>

// ---------------- problem constants ----------------
#define BBATCH 64
#define SSEQ   256
#define HHID   256
#define MROWS  16384
#define BTROWS 16384

// ---------------- fp32 scratch ----------------
#define O_XGF   ((size_t)0)
#define SZ_XG   ((size_t)MROWS*1024)
#define O_XGB   (O_XGF+SZ_XG)
#define O_HID   (O_XGB+SZ_XG)
#define SZ_HID  ((size_t)BTROWS*512)
#define O_RHID  (O_HID+SZ_HID)
#define O_WHHT  (O_RHID+SZ_HID)
#define SZ_WHHT ((size_t)HHID*HHID*4)
#define O_HTF   (O_WHHT+4*SZ_WHHT)
#define SZ_HT   ((size_t)2*HHID*BBATCH)
#define O_HTB   (O_HTF+SZ_HT)
#define O_OWT   (O_HTB+SZ_HT)
#define SZ_OWT  ((size_t)512*96)
#define O_BS1   (O_OWT+SZ_OWT)
#define O_BS2   (O_BS1+2048)
#define O_BSM   (O_BS2+2048)
#define F32_TOTAL (O_BSM+1024)

__device__ float g_f32[F32_TOTAL];

// ---------------- bf16 scratch ----------------
#define B_IVHI ((size_t)0)
#define SZ_IV  ((size_t)MROWS*192)
#define B_IVLO (B_IVHI+SZ_IV)
#define B_AVHI (B_IVLO+SZ_IV)
#define SZ_AV  ((size_t)MROWS*512)
#define B_AVLO (B_AVHI+SZ_AV)
#define B_V2HI (B_AVLO+SZ_AV)
#define B_V2LO (B_V2HI+SZ_AV)
#define B_W1HI (B_V2LO+SZ_AV)
#define SZ_W1  ((size_t)2048*192)
#define B_W1LO (B_W1HI+SZ_W1)
#define B_W2HI (B_W1LO+SZ_W1)
#define SZ_W2  ((size_t)2048*512)
#define B_W2LO (B_W2HI+SZ_W2)
#define B_WMHI (B_W2LO+SZ_W2)
#define SZ_WM  ((size_t)1024*6144)
#define B_WMLO (B_WMHI+SZ_WM)
#define BF_TOTAL (B_WMLO+SZ_WM)

__device__ __nv_bfloat16 g_bf[BF_TOTAL];

// per-direction grid barrier state
__device__ unsigned g_cnt2[2];
__device__ volatile unsigned g_flag2[2];

// ---------------- small prep kernels ----------------
__global__ void k_embed_split(const int* __restrict__ wid, const int* __restrict__ pid,
                              const float* __restrict__ wl, const float* __restrict__ pl,
                              __nv_bfloat16* __restrict__ hi, __nv_bfloat16* __restrict__ lo)
{
    int i = blockIdx.x * 256 + threadIdx.x;
    if (i >= MROWS * 192) return;
    int col = i % 192, bs = i / 192;
    float v = 0.f;
    if (col < 128)      v = wl[(size_t)wid[bs] * 128 + col];
    else if (col < 160) v = pl[(size_t)pid[bs] * 32 + (col - 128)];
    __nv_bfloat16 h = __float2bfloat16(v);
    hi[i] = h;
    lo[i] = __float2bfloat16(v - __bfloat162float(h));
}

__global__ void k_wsplit(const float* __restrict__ W0, const float* __restrict__ W1,
                         int N0, int Ksrc, int Kpad,
                         __nv_bfloat16* __restrict__ hi, __nv_bfloat16* __restrict__ lo, int total)
{
    int i = blockIdx.x * 256 + threadIdx.x;
    if (i >= total) return;
    int row = i / Kpad, col = i % Kpad;
    float v = 0.f;
    if (col < Ksrc)
        v = (row < N0) ? W0[(size_t)row * Ksrc + col]
                       : W1[(size_t)(row - N0) * Ksrc + col];
    __nv_bfloat16 h = __float2bfloat16(v);
    hi[i] = h;
    lo[i] = __float2bfloat16(v - __bfloat162float(h));
}

__global__ void k_bias2(const float* a, const float* b, const float* c, const float* d,
                        float* __restrict__ o)
{
    int i = blockIdx.x * 256 + threadIdx.x;
    if (i >= 2048) return;
    o[i] = (i < 1024) ? a[i] + b[i] : c[i - 1024] + d[i - 1024];
}

__global__ void k_bcat(const float* a, const float* b, float* __restrict__ o)
{
    int i = blockIdx.x * 256 + threadIdx.x;
    if (i >= 1024) return;
    o[i] = (i < 512) ? a[i] : b[i - 512];
}

__global__ void k_whht(const float* __restrict__ w, float* __restrict__ o)
{
    int i = blockIdx.x * 256 + threadIdx.x;
    if (i >= HHID * HHID * 4) return;
    int k = i >> 10, rem = i & 1023, jh = rem >> 2, g = rem & 3;
    o[i] = w[((g << 8) + jh) * HHID + k];
}

__global__ void k_owt(const float* __restrict__ outL, const float* __restrict__ routL,
                      float* __restrict__ owT)
{
    int i = blockIdx.x * 256 + threadIdx.x;
    if (i >= 512 * 96) return;
    int h = i / 96, o = i % 96;
    owT[i] = (o < 3) ? outL[o * 512 + h] : routL[(o - 3) * 512 + h];
}

__global__ void k_reset(float* __restrict__ hTf, float* __restrict__ hTb)
{
    int i = blockIdx.x * 256 + threadIdx.x;
    if (i == 0) { g_cnt2[0] = 0; g_cnt2[1] = 0; g_flag2[0] = 0; g_flag2[1] = 0; }
    if (i < 2 * (int)SZ_HT) {
        if (i < (int)SZ_HT) hTf[i] = 0.f;
        else                hTb[i - SZ_HT] = 0.f;
    }
}

// ---------------- persistent biLSTM recurrence -------------------------------
// 128 blocks: 0..63 fwd, 64..127 bwd; per-direction barrier (64 arrivals).
// Output written directly as bf16 hi/lo split [MROWS, 512].
__global__ void __launch_bounds__(256, 1) k_recur(
    const float* __restrict__ xgf, const float* __restrict__ xgb,
    const float* __restrict__ wtf, const float* __restrict__ wtb,
    __nv_bfloat16* __restrict__ vhi, __nv_bfloat16* __restrict__ vlo,
    float* __restrict__ hTf, float* __restrict__ hTb)
{
    extern __shared__ char s_raw[];
    float* sm = (float*)s_raw;
    float* sh_w = sm;            // [256 k][16 jh][4 gates]
    float* sh_h = sm + 16384;    // [256 k][16 b]

    const int tid = threadIdx.x;
    const int dir = blockIdx.x >> 6;
    const int sub = blockIdx.x & 63;
    const int b0  = (sub & 3) * 16;
    const int jh0 = (sub >> 2) * 16;
    const int bl  = tid >> 4, jhl = tid & 15;
    const int b   = b0 + bl,  jh  = jh0 + jhl;

    const float* xg = dir ? xgb : xgf;
    const float* wt = dir ? wtb : wtf;
    float*       hT = dir ? hTb : hTf;

    for (int idx = tid; idx < 16384; idx += 256) {
        int k = idx >> 6, r = idx & 63;
        sh_w[idx] = wt[k * 1024 + jh0 * 4 + r];
    }

    float c = 0.f;
    unsigned epoch = 0;
    __syncthreads();

    for (int it = 0; it < SSEQ; ++it) {
        const float* hcur = hT + (it & 1) * (HHID * BBATCH);
        float*       hnxt = hT + ((it & 1) ^ 1) * (HHID * BBATCH);

        for (int idx = tid; idx < 4096; idx += 256) {
            int k = idx >> 4, bb = idx & 15;
            sh_h[idx] = __ldcg(hcur + k * 64 + b0 + bb);
        }
        __syncthreads();

        const int s = dir ? (SSEQ - 1 - it) : it;
        const float* xr = xg + ((size_t)(b * SSEQ + s)) * 1024 + jh;
        float ai = __ldg(xr +   0);
        float af = __ldg(xr + 256);
        float ag = __ldg(xr + 512);
        float ao = __ldg(xr + 768);

        const float* whp = sh_w + jhl * 4;
        const float* shp = sh_h + bl;
        #pragma unroll 8
        for (int k = 0; k < HHID; ++k) {
            float  hv = shp[k * 16];
            float4 w  = *reinterpret_cast<const float4*>(whp + k * 64);
            ai = fmaf(hv, w.x, ai);
            af = fmaf(hv, w.y, af);
            ag = fmaf(hv, w.z, ag);
            ao = fmaf(hv, w.w, ao);
        }

        float ig = 1.f / (1.f + expf(-ai));
        float fg = 1.f / (1.f + expf(-af));
        float gv = tanhf(ag);
        float og = 1.f / (1.f + expf(-ao));
        c = fmaf(fg, c, ig * gv);
        float h = og * tanhf(c);

        size_t off = ((size_t)(b * SSEQ + s)) * 512 + (dir << 8) + jh;
        __nv_bfloat16 hh = __float2bfloat16(h);
        vhi[off] = hh;
        vlo[off] = __float2bfloat16(h - __bfloat162float(hh));
        __stcg(hnxt + jh * 64 + b, h);

        // ---- per-direction software grid barrier ----
        __threadfence();
        __syncthreads();
        epoch += 64;
        if (tid == 0) {
            unsigned arrived = atomicAdd(&g_cnt2[dir], 1) + 1;
            if (arrived == epoch) {
                __threadfence();
                g_flag2[dir] = epoch;
            } else {
                while (g_flag2[dir] < epoch) { }
                __threadfence();
            }
        }
        __syncthreads();
    }
}

// ---------------- HMMA bf16 3-product split GEMM, cp.async pipelined --------
// C[m][n] = sum_k A[m][k]*W[n][k] + bias[n]; A ~ Ahi+Alo, W ~ Whi+Wlo.
// Block tile 128x128, 8 warps (warp tile 32x64), K-chunk 32, 3-stage cp.async.
// SMEM rows 32 bf16 + pad -> 80 B (20 words): conflict-free frags, 16B aligned.
#define KC    32
#define TROWB 80
#define TILE2 10240       // 128 * 80
#define STG   40960       // 4 tiles per stage
#define NST   3

__device__ __forceinline__ uint32_t smem_u32(const void* p) {
    uint32_t a;
    asm("{ .reg .u64 t; cvta.to.shared.u64 t, %1; cvt.u32.u64 %0, t; }"
        : "=r"(a) : "l"(p));
    return a;
}
__device__ __forceinline__ void cpasync16(uint32_t dst, const void* src) {
    asm volatile("cp.async.ca.shared.global [%0], [%1], 16;" :: "r"(dst), "l"(src));
}
#define CP_COMMIT() asm volatile("cp.async.commit_group;" ::: "memory")
#define CP_WAIT1()  asm volatile("cp.async.wait_group 1;" ::: "memory")
#define CP_WAIT0()  asm volatile("cp.async.wait_group 0;" ::: "memory")

__device__ __forceinline__ void mma16816(float* d, const uint32_t* a, const uint32_t* b) {
    asm volatile(
        "mma.sync.aligned.m16n8k16.row.col.f32.bf16.bf16.f32 "
        "{%0,%1,%2,%3}, {%4,%5,%6,%7}, {%8,%9}, {%0,%1,%2,%3};"
        : "+f"(d[0]), "+f"(d[1]), "+f"(d[2]), "+f"(d[3])
        : "r"(a[0]), "r"(a[1]), "r"(a[2]), "r"(a[3]), "r"(b[0]), "r"(b[1]));
}

template<bool GATHER>
__device__ __forceinline__ void issue_stage(
    uint32_t sbase, int stage, int c, int row0, int n0, int KU,
    const uint4* A4h, const uint4* A4l, const uint4* W4h, const uint4* W4l,
    const int* fidx, int tid)
{
    const int k0 = c * KC;
    const uint32_t dstb = sbase + stage * STG;
    #pragma unroll
    for (int u0 = 0; u0 < 2048; u0 += 256) {
        int u = u0 + tid;
        int tile = u >> 9;
        int v = u & 511;
        int r = v >> 2, j = v & 3;
        const uint4* src;
        if (tile < 2) {
            const uint4* base = tile ? A4l : A4h;
            if (GATHER) {
                int m    = row0 + r;
                int slot = k0 >> 9;
                int fi   = __ldg(fidx + m * 12 + slot);
                int srow = ((m >> 8) << 8) + fi;
                src = base + (size_t)srow * 64 + ((k0 & 511) >> 3) + j;
            } else {
                src = base + (size_t)(row0 + r) * KU + (k0 >> 3) + j;
            }
        } else {
            const uint4* base = (tile == 3) ? W4l : W4h;
            src = base + (size_t)(n0 + r) * KU + (k0 >> 3) + j;
        }
        cpasync16(dstb + tile * TILE2 + r * TROWB + j * 16, src);
    }
    CP_COMMIT();
}

template<bool GATHER, bool TANH>
__global__ void __launch_bounds__(256, 1) k_hmma(
    const __nv_bfloat16* __restrict__ Ahi, const __nv_bfloat16* __restrict__ Alo,
    const __nv_bfloat16* __restrict__ Whi, const __nv_bfloat16* __restrict__ Wlo,
    const float* __restrict__ bias, float* __restrict__ C0, float* __restrict__ C1,
    int halfN, int Kpad, const int* __restrict__ fidx)
{
    extern __shared__ __align__(16) char smem[];
    const uint32_t sb = smem_u32(smem);
    const int tid  = threadIdx.x;
    const int wid  = tid >> 5;
    const int lane = tid & 31;
    const int grp  = lane >> 2;
    const int quad = lane & 3;
    const int row0 = blockIdx.y * 128;
    const int n0   = blockIdx.x * 128;
    const int wm   = (wid & 3) * 32;
    const int wn   = (wid >> 2) * 64;

    const int KU = Kpad >> 3;
    const uint4* A4h = (const uint4*)Ahi;
    const uint4* A4l = (const uint4*)Alo;
    const uint4* W4h = (const uint4*)Whi;
    const uint4* W4l = (const uint4*)Wlo;

    float acc[2][8][4];
    #pragma unroll
    for (int i = 0; i < 2; ++i)
        #pragma unroll
        for (int j = 0; j < 8; ++j)
            #pragma unroll
            for (int q = 0; q < 4; ++q) acc[i][j][q] = 0.f;

    const int nch = Kpad / KC;
    issue_stage<GATHER>(sb, 0, 0, row0, n0, KU, A4h, A4l, W4h, W4l, fidx, tid);
    issue_stage<GATHER>(sb, 1, 1, row0, n0, KU, A4h, A4l, W4h, W4l, fidx, tid);

    for (int c = 0; c < nch; ++c) {
        if (c + 1 < nch) { CP_WAIT1(); } else { CP_WAIT0(); }
        __syncthreads();
        if (c + 2 < nch)
            issue_stage<GATHER>(sb, (c + 2) % NST, c + 2, row0, n0, KU,
                                A4h, A4l, W4h, W4l, fidx, tid);

        const char* buf = smem + (c % NST) * STG;
        #pragma unroll
        for (int p = 0; p < 3; ++p) {
            const uint32_t* A32 = (const uint32_t*)(buf + (p == 2 ? 1 : 0) * TILE2);
            const uint32_t* B32 = (const uint32_t*)(buf + (p == 1 ? 3 : 2) * TILE2);
            #pragma unroll
            for (int ks = 0; ks < 2; ++ks) {
                const int kw = ks * 8 + quad;
                uint32_t a[2][4];
                #pragma unroll
                for (int mt = 0; mt < 2; ++mt) {
                    int r = wm + mt * 16 + grp;
                    a[mt][0] = A32[r * 20 + kw];
                    a[mt][1] = A32[(r + 8) * 20 + kw];
                    a[mt][2] = A32[r * 20 + kw + 4];
                    a[mt][3] = A32[(r + 8) * 20 + kw + 4];
                }
                uint32_t b[8][2];
                #pragma unroll
                for (int nt = 0; nt < 8; ++nt) {
                    int n = wn + nt * 8 + grp;
                    b[nt][0] = B32[n * 20 + kw];
                    b[nt][1] = B32[n * 20 + kw + 4];
                }
                #pragma unroll
                for (int mt = 0; mt < 2; ++mt)
                    #pragma unroll
                    for (int nt = 0; nt < 8; ++nt)
                        mma16816(acc[mt][nt], a[mt], b[nt]);
            }
        }
    }

    // ---- epilogue: bias (+tanh), route to C0/C1 ----
    const int gbase = n0 + wn;
    float* Co;
    int cbase;
    if (gbase < halfN) { Co = C0; cbase = gbase; }
    else               { Co = C1; cbase = gbase - halfN; }

    #pragma unroll
    for (int mt = 0; mt < 2; ++mt) {
        int r = row0 + wm + mt * 16 + grp;
        #pragma unroll
        for (int nt = 0; nt < 8; ++nt) {
            int gc = gbase + nt * 8 + quad * 2;
            float b0v = bias[gc], b1v = bias[gc + 1];
            float v0 = acc[mt][nt][0] + b0v;
            float v1 = acc[mt][nt][1] + b1v;
            float v2 = acc[mt][nt][2] + b0v;
            float v3 = acc[mt][nt][3] + b1v;
            if (TANH) { v0 = tanhf(v0); v1 = tanhf(v1); v2 = tanhf(v2); v3 = tanhf(v3); }
            int cc = cbase + nt * 8 + quad * 2;
            *(float2*)(Co + (size_t)r * halfN + cc)       = make_float2(v0, v1);
            *(float2*)(Co + (size_t)(r + 8) * halfN + cc) = make_float2(v2, v3);
        }
    }
}

// ---------------- output head ------------------------------------------------
__global__ void k_out(const float* __restrict__ hid, const float* __restrict__ rhid,
                      const float* __restrict__ owT, const float* __restrict__ ob,
                      const float* __restrict__ rb, float* __restrict__ out)
{
    int bt = blockIdx.x;
    __shared__ float sh[1024];
    for (int i = threadIdx.x; i < 512; i += 128) sh[i]       = hid[(size_t)bt * 512 + i];
    for (int i = threadIdx.x; i < 512; i += 128) sh[512 + i] = rhid[(size_t)bt * 512 + i];
    __syncthreads();
    int o = threadIdx.x;
    if (o < 96) {
        const float* base = (o < 3) ? sh : sh + 512;
        float acc = 0.f;
        #pragma unroll 8
        for (int h = 0; h < 512; ++h)
            acc = fmaf(owT[h * 96 + o], base[h], acc);
        if (o < 3) out[(size_t)bt * 3 + o] = acc + ob[o];
        else       out[(size_t)BTROWS * 3 + (size_t)bt * 93 + (o - 3)] = acc + rb[o - 3];
    }
}

// ---------------- launch ------------------------------------------------------
extern "C" void kernel_launch(void* const* d_in, const int* in_sizes, int n_in,
                              void* d_out, int out_size)
{
    const int*   wid   = (const int*)d_in[0];
    const int*   pid   = (const int*)d_in[1];
    const int*   fidx  = (const int*)d_in[2];
    const float* wl    = (const float*)d_in[3];
    const float* pl    = (const float*)d_in[4];
    const float* Wih1f = (const float*)d_in[5];
    const float* Whh1f = (const float*)d_in[6];
    const float* bih1f = (const float*)d_in[7];
    const float* bhh1f = (const float*)d_in[8];
    const float* Wih1b = (const float*)d_in[9];
    const float* Whh1b = (const float*)d_in[10];
    const float* bih1b = (const float*)d_in[11];
    const float* bhh1b = (const float*)d_in[12];
    const float* Wih2f = (const float*)d_in[13];
    const float* Whh2f = (const float*)d_in[14];
    const float* bih2f = (const float*)d_in[15];
    const float* bhh2f = (const float*)d_in[16];
    const float* Wih2b = (const float*)d_in[17];
    const float* Whh2b = (const float*)d_in[18];
    const float* bih2b = (const float*)d_in[19];
    const float* bhh2b = (const float*)d_in[20];
    const float* hidL  = (const float*)d_in[21];
    const float* hidB  = (const float*)d_in[22];
    const float* outL  = (const float*)d_in[23];
    const float* outB  = (const float*)d_in[24];
    const float* rhidL = (const float*)d_in[25];
    const float* rhidB = (const float*)d_in[26];
    const float* routL = (const float*)d_in[27];
    const float* routB = (const float*)d_in[28];
    float* out = (float*)d_out;

    float* scr = nullptr;
    cudaGetSymbolAddress((void**)&scr, g_f32);
    __nv_bfloat16* bfp = nullptr;
    cudaGetSymbolAddress((void**)&bfp, g_bf);

    float* xgf  = scr + O_XGF;
    float* xgb  = scr + O_XGB;
    float* hid  = scr + O_HID;
    float* rhid = scr + O_RHID;
    float* whht = scr + O_WHHT;
    float* hTf  = scr + O_HTF;
    float* hTb  = scr + O_HTB;
    float* owT  = scr + O_OWT;
    float* bs1  = scr + O_BS1;
    float* bs2  = scr + O_BS2;
    float* bsm  = scr + O_BSM;

    __nv_bfloat16* ivhi = bfp + B_IVHI;
    __nv_bfloat16* ivlo = bfp + B_IVLO;
    __nv_bfloat16* avhi = bfp + B_AVHI;
    __nv_bfloat16* avlo = bfp + B_AVLO;
    __nv_bfloat16* v2hi = bfp + B_V2HI;
    __nv_bfloat16* v2lo = bfp + B_V2LO;
    __nv_bfloat16* w1hi = bfp + B_W1HI;
    __nv_bfloat16* w1lo = bfp + B_W1LO;
    __nv_bfloat16* w2hi = bfp + B_W2HI;
    __nv_bfloat16* w2lo = bfp + B_W2LO;
    __nv_bfloat16* wmhi = bfp + B_WMHI;
    __nv_bfloat16* wmlo = bfp + B_WMLO;

    cudaFuncSetAttribute(k_recur, cudaFuncAttributeMaxDynamicSharedMemorySize, 81920);
    cudaFuncSetAttribute(k_hmma<false, false>, cudaFuncAttributeMaxDynamicSharedMemorySize, NST * STG);
    cudaFuncSetAttribute(k_hmma<true, true>,  cudaFuncAttributeMaxDynamicSharedMemorySize, NST * STG);

    // --- prep ---
    k_embed_split<<<(MROWS * 192 + 255) / 256, 256>>>(wid, pid, wl, pl, ivhi, ivlo);
    k_whht<<<1024, 256>>>(Whh1f, whht + 0 * SZ_WHHT);
    k_whht<<<1024, 256>>>(Whh1b, whht + 1 * SZ_WHHT);
    k_whht<<<1024, 256>>>(Whh2f, whht + 2 * SZ_WHHT);
    k_whht<<<1024, 256>>>(Whh2b, whht + 3 * SZ_WHHT);
    k_owt<<<(512 * 96 + 255) / 256, 256>>>(outL, routL, owT);
    k_wsplit<<<(2048 * 192 + 255) / 256, 256>>>(Wih1f, Wih1b, 1024, 160, 192, w1hi, w1lo, 2048 * 192);
    k_wsplit<<<(2048 * 512 + 255) / 256, 256>>>(Wih2f, Wih2b, 1024, 512, 512, w2hi, w2lo, 2048 * 512);
    k_wsplit<<<(1024 * 6144 + 255) / 256, 256>>>(hidL, rhidL, 512, 6144, 6144, wmhi, wmlo, 1024 * 6144);
    k_bias2<<<8, 256>>>(bih1f, bhh1f, bih1b, bhh1b, bs1);
    k_bias2<<<8, 256>>>(bih2f, bhh2f, bih2b, bhh2b, bs2);
    k_bcat<<<4, 256>>>(hidB, rhidB, bsm);

    // --- layer 1: xg (both directions fused, N=2048), recurrence ---
    dim3 gx(16, 128);
    k_hmma<false, false><<<gx, 256, NST * STG>>>(ivhi, ivlo, w1hi, w1lo, bs1, xgf, xgb, 1024, 192, nullptr);
    k_reset<<<256, 256>>>(hTf, hTb);
    k_recur<<<128, 256, 81920>>>(xgf, xgb, whht + 0 * SZ_WHHT, whht + 1 * SZ_WHHT, avhi, avlo, hTf, hTb);

    // --- layer 2 ---
    k_hmma<false, false><<<gx, 256, NST * STG>>>(avhi, avlo, w2hi, w2lo, bs2, xgf, xgb, 1024, 512, nullptr);
    k_reset<<<256, 256>>>(hTf, hTb);
    k_recur<<<128, 256, 81920>>>(xgf, xgb, whht + 2 * SZ_WHHT, whht + 3 * SZ_WHHT, v2hi, v2lo, hTf, hTb);

    // --- MLP head: gathered GEMM (hid|rhid fused, N=1024), tanh epilogue ---
    dim3 gm(8, 128);
    k_hmma<true, true><<<gm, 256, NST * STG>>>(v2hi, v2lo, wmhi, wmlo, bsm, hid, rhid, 512, 6144, fidx);

    // --- output head ---
    k_out<<<BTROWS, 128>>>(hid, rhid, owT, outB, routB, out);
}